// round 9
// baseline (speedup 1.0000x reference)
#include <cuda_runtime.h>
#include <cuda_fp16.h>
#include <cstdint>

// ===================== problem sizes =====================
static constexpr int  B_   = 8192;
static constexpr int  C_   = 12;
static constexpr int  A_   = 8;
static constexpr int  DI   = 1024;
static constexpr int  DO   = 1024;
static constexpr int  NTOT = C_ * DO;        // 12288
static constexpr long NX   = (long)B_ * DI;      // 8388608
static constexpr long NW   = (long)NTOT * DI;    // 12582912

// ===================== device scratch (no allocs allowed) ====================
// main  (f16, f32 acc):  xh . wh                        (K=1024, 32 iters k16)
// cross (fp8 e4m3, f32 acc): [xh8|xl8] . [wl8|wh8]      (K=2048, 32 iters k32)
//   xh8 = xh*2^4, xl8 = xl*2^16, wl8 = wl*2^21, wh8 = wh*2^9
//   both product streams at scale 2^25 -> one dequant * 2^-25
__device__ __half  g_xh[(size_t)B_ * DI];          // 16 MB (row = 2048 B)
__device__ __half  g_wh[(size_t)NTOT * DI];        // 24 MB (row = 2048 B)
__device__ uint8_t g_x8[(size_t)B_ * 2 * DI];      // 16 MB [xh8 | xl8]
__device__ uint8_t g_w8[(size_t)NTOT * 2 * DI];    // 24 MB [wl8 | wh8]
__device__ float   g_u[(size_t)B_ * NTOT];         // 402 MB
__device__ float   g_ent[B_];

// ===================== helpers =====================
__device__ __forceinline__ uint32_t smem_u32(const void* p) {
    uint32_t a;
    asm("{ .reg .u64 t; cvta.to.shared.u64 t, %1; cvt.u32.u64 %0, t; }" : "=r"(a) : "l"(p));
    return a;
}
__device__ __forceinline__ void cp_async16(uint32_t smem_dst, const void* gsrc) {
    asm volatile("cp.async.cg.shared.global [%0], [%1], 16;" :: "r"(smem_dst), "l"(gsrc));
}
#define CP_COMMIT() asm volatile("cp.async.commit_group;" ::: "memory")
#define CP_WAIT(n)  asm volatile("cp.async.wait_group %0;" :: "n"(n) : "memory")

#define LDSM_X4(R0,R1,R2,R3,ADDR) \
    asm volatile("ldmatrix.sync.aligned.m8n8.x4.shared.b16 {%0,%1,%2,%3}, [%4];" \
                 : "=r"(R0),"=r"(R1),"=r"(R2),"=r"(R3) : "r"(ADDR))

#define MMA16816(C0,C1,C2,C3,A0,A1,A2,A3,B0,B1) \
    asm volatile("mma.sync.aligned.m16n8k16.row.col.f32.f16.f16.f32 " \
                 "{%0,%1,%2,%3}, {%4,%5,%6,%7}, {%8,%9}, {%0,%1,%2,%3};" \
                 : "+f"(C0),"+f"(C1),"+f"(C2),"+f"(C3) \
                 : "r"(A0),"r"(A1),"r"(A2),"r"(A3),"r"(B0),"r"(B1))

// fp8 e4m3, K=32, f32 accumulator — baseline PTX (sm_89+)
#define MMAF8(C0,C1,C2,C3,A0,A1,A2,A3,B0,B1) \
    asm volatile("mma.sync.aligned.m16n8k32.row.col.f32.e4m3.e4m3.f32 " \
                 "{%0,%1,%2,%3}, {%4,%5,%6,%7}, {%8,%9}, {%0,%1,%2,%3};" \
                 : "+f"(C0),"+f"(C1),"+f"(C2),"+f"(C3) \
                 : "r"(A0),"r"(A1),"r"(A2),"r"(A3),"r"(B0),"r"(B1))

__device__ __forceinline__ uint8_t f2e4m3(float v) {
    uint16_t r;
    asm("cvt.rn.satfinite.e4m3x2.f32 %0, %1, %2;" : "=h"(r) : "f"(0.f), "f"(v));
    return (uint8_t)r;   // low byte = convert of second source
}

// ===================== kernel 1: split + fp8 quantize =====================
__global__ __launch_bounds__(256) void split_kernel(const float* __restrict__ x,
                                                    const float* __restrict__ W) {
    long i = (long)blockIdx.x * 256 + threadIdx.x;
    if (i < NX) {
        long b = i >> 10, k = i & 1023;
        float v = x[i];
        __half h = __float2half_rn(v);
        float hf = __half2float(h);
        float l = v - hf;
        g_xh[i] = h;
        size_t qb = (size_t)b * 2048;
        g_x8[qb + k]        = f2e4m3(hf * 16.f);       // xh * 2^4
        g_x8[qb + 1024 + k] = f2e4m3(l * 65536.f);     // xl * 2^16
    } else {
        long j = i - NX;
        if (j < NW) {
            long n = j >> 10, k = j & 1023;
            float v = W[j];
            __half h = __float2half_rn(v);
            float hf = __half2float(h);
            float l = v - hf;
            g_wh[j] = h;
            size_t qb = (size_t)n * 2048;
            g_w8[qb + k]        = f2e4m3(l * 2097152.f);  // wl * 2^21
            g_w8[qb + 1024 + k] = f2e4m3(hf * 512.f);     // wh * 2^9
        }
    }
}

// ===================== kernel 2: fp8/f16 GEMM  u = x @ W^T + bias =============
// CTA 128x256, 8 warps (2m x 4n) of 64x64, 64B data rows (+16B pad = 80B
// stride, conflict-free ldmatrix). Phase 1: 32 iters fp8 k32 (cross, K=2048).
// Phase 2: 32 iters f16 k16 (main, K=1024). One f32 accumulator throughout.
static constexpr int TM = 128, TN = 256, STAGES = 4;
static constexpr int ROWB = 80;
static constexpr int ASTG = TM * ROWB;            // 10240
static constexpr int BSTG = TN * ROWB;            // 20480
static constexpr int STG  = ASTG + BSTG;          // 30720
static constexpr int GEMM_SMEM = STAGES * STG;    // 122880
static constexpr int KI = 32;                     // fp8 iters
static constexpr int KT = 64;                     // + 32 f16 iters

__global__ __launch_bounds__(256, 1) void gemm_kernel(const float* __restrict__ bias) {
    extern __shared__ char sm[];
    const uint32_t sb = smem_u32(sm);
    const int tid  = threadIdx.x;
    const int lane = tid & 31;
    const int w    = tid >> 5;
    const int wm   = w & 1;
    const int wn   = w >> 1;
    const long m0  = (long)blockIdx.y * TM;
    const long n0  = (long)blockIdx.x * TN;

    float acc[4][8][4];
    #pragma unroll
    for (int mt = 0; mt < 4; mt++)
        #pragma unroll
        for (int nt = 0; nt < 8; nt++)
            #pragma unroll
            for (int e = 0; e < 4; e++) acc[mt][nt][e] = 0.f;

    // ldmatrix per-lane bases (identical both phases; validated in R6 for k32 bytes)
    const uint32_t rowA = (uint32_t)(wm * 64 + (lane & 7) + ((lane >> 3) & 1) * 8);
    const uint32_t colA = (uint32_t)(((lane >> 4) & 1) * 16);
    const uint32_t rowB = (uint32_t)(wn * 64 + (lane & 7) + ((lane >> 4) & 1) * 8);
    const uint32_t colB = (uint32_t)(((lane >> 3) & 1) * 16);

    // per-iter row = 64 data bytes = 4x16B granules; A 512 granules, B 1024.
    auto load_stage = [&](int j) {
        const uint32_t As = sb + (uint32_t)((j & 3) * STG);
        const uint32_t Bs = As + ASTG;
        const char* srcA = (j < KI) ? (const char*)g_x8 : (const char*)g_xh;
        const char* srcB = (j < KI) ? (const char*)g_w8 : (const char*)g_wh;
        const int kb = (j & 31) * 64;   // byte offset within 2048-byte row
        #pragma unroll
        for (int it = 0; it < 2; it++) {
            int idx = tid + it * 256;             // < 512
            int r = idx >> 2, c = idx & 3;
            cp_async16(As + r * ROWB + c * 16, srcA + (size_t)(m0 + r) * 2048 + kb + c * 16);
        }
        #pragma unroll
        for (int it = 0; it < 4; it++) {
            int idx = tid + it * 256;             // < 1024
            int r = idx >> 2, c = idx & 3;
            cp_async16(Bs + r * ROWB + c * 16, srcB + (size_t)(n0 + r) * 2048 + kb + c * 16);
        }
    };

    #pragma unroll
    for (int j = 0; j < STAGES - 1; j++) { load_stage(j); CP_COMMIT(); }

    // -------- phase 1: fp8 cross terms (product scale 2^25) --------
    #pragma unroll 1
    for (int i = 0; i < KI; i++) {
        CP_WAIT(STAGES - 2);
        __syncthreads();
        load_stage(i + STAGES - 1);
        CP_COMMIT();
        const uint32_t As = sb + (uint32_t)((i & 3) * STG);
        const uint32_t Bs = As + ASTG;
        #pragma unroll
        for (int ks = 0; ks < 2; ks++) {
            uint32_t a[4][4], b[8][2];
            #pragma unroll
            for (int mt = 0; mt < 4; mt++) {
                uint32_t ad = As + (rowA + mt * 16) * ROWB + ks * 32 + colA;
                LDSM_X4(a[mt][0], a[mt][1], a[mt][2], a[mt][3], ad);
            }
            #pragma unroll
            for (int p = 0; p < 4; p++) {
                uint32_t bd = Bs + (rowB + p * 16) * ROWB + ks * 32 + colB;
                LDSM_X4(b[2*p][0], b[2*p][1], b[2*p+1][0], b[2*p+1][1], bd);
            }
            #pragma unroll
            for (int mt = 0; mt < 4; mt++)
                #pragma unroll
                for (int nt = 0; nt < 8; nt++)
                    MMAF8(acc[mt][nt][0], acc[mt][nt][1], acc[mt][nt][2], acc[mt][nt][3],
                          a[mt][0], a[mt][1], a[mt][2], a[mt][3],
                          b[nt][0], b[nt][1]);
        }
    }

    // dequant cross contribution: * 2^-25 (in place; same f32 accumulators)
    #pragma unroll
    for (int mt = 0; mt < 4; mt++)
        #pragma unroll
        for (int nt = 0; nt < 8; nt++)
            #pragma unroll
            for (int e = 0; e < 4; e++)
                acc[mt][nt][e] *= (1.f / 33554432.f);

    // -------- phase 2: f16 main term --------
    #pragma unroll 1
    for (int i = KI; i < KT; i++) {
        CP_WAIT(STAGES - 2);
        __syncthreads();
        if (i + STAGES - 1 < KT) load_stage(i + STAGES - 1);
        CP_COMMIT();
        const uint32_t As = sb + (uint32_t)((i & 3) * STG);
        const uint32_t Bs = As + ASTG;
        #pragma unroll
        for (int ks = 0; ks < 2; ks++) {
            uint32_t a[4][4], b[8][2];
            #pragma unroll
            for (int mt = 0; mt < 4; mt++) {
                uint32_t ad = As + (rowA + mt * 16) * ROWB + ks * 32 + colA;
                LDSM_X4(a[mt][0], a[mt][1], a[mt][2], a[mt][3], ad);
            }
            #pragma unroll
            for (int p = 0; p < 4; p++) {
                uint32_t bd = Bs + (rowB + p * 16) * ROWB + ks * 32 + colB;
                LDSM_X4(b[2*p][0], b[2*p][1], b[2*p+1][0], b[2*p+1][1], bd);
            }
            #pragma unroll
            for (int mt = 0; mt < 4; mt++)
                #pragma unroll
                for (int nt = 0; nt < 8; nt++)
                    MMA16816(acc[mt][nt][0], acc[mt][nt][1], acc[mt][nt][2], acc[mt][nt][3],
                             a[mt][0], a[mt][1], a[mt][2], a[mt][3],
                             b[nt][0], b[nt][1]);
        }
    }

    // epilogue: add bias, store fp32 to g_u
    #pragma unroll
    for (int nt = 0; nt < 8; nt++) {
        const long n = n0 + wn * 64 + nt * 8 + 2 * (lane & 3);
        const float2 bz = *(const float2*)&bias[n];
        #pragma unroll
        for (int mt = 0; mt < 4; mt++) {
            const long m = m0 + wm * 64 + mt * 16 + (lane >> 2);
            float2 lo = { acc[mt][nt][0] + bz.x, acc[mt][nt][1] + bz.y };
            float2 hi = { acc[mt][nt][2] + bz.x, acc[mt][nt][3] + bz.y };
            *(float2*)&g_u[(size_t)m * NTOT + n]       = lo;
            *(float2*)&g_u[(size_t)(m + 8) * NTOT + n] = hi;
        }
    }
}

// ===================== kernel 3: fused routing =====================
__device__ __forceinline__ float block_sum(float v, volatile float* smr) {
    int lane = threadIdx.x & 31, w = threadIdx.x >> 5;
    #pragma unroll
    for (int o = 16; o; o >>= 1) v += __shfl_xor_sync(0xffffffffu, v, o);
    if (lane == 0) smr[w] = v;
    __syncthreads();
    if (threadIdx.x == 0) {
        float s = smr[0];
        #pragma unroll
        for (int i = 1; i < 8; i++) s += smr[i];
        smr[8] = s;
    }
    __syncthreads();
    float r = smr[8];
    __syncthreads();
    return r;
}
__device__ __forceinline__ float block_max(float v, volatile float* smr) {
    int lane = threadIdx.x & 31, w = threadIdx.x >> 5;
    #pragma unroll
    for (int o = 16; o; o >>= 1) v = fmaxf(v, __shfl_xor_sync(0xffffffffu, v, o));
    if (lane == 0) smr[w] = v;
    __syncthreads();
    if (threadIdx.x == 0) {
        float s = smr[0];
        #pragma unroll
        for (int i = 1; i < 8; i++) s = fmaxf(s, smr[i]);
        smr[8] = s;
    }
    __syncthreads();
    float r = smr[8];
    __syncthreads();
    return r;
}

__global__ __launch_bounds__(256) void routing_kernel(float* __restrict__ out) {
    __shared__ float sred[9];
    __shared__ float s12[8 * 12];
    __shared__ float sb12[12];
    const int b = blockIdx.x;
    const int t = threadIdx.x;
    const int lid = t & 31, wid = t >> 5;

    float ur[12][4];
    const float* ub = g_u + (size_t)b * NTOT;
    #pragma unroll
    for (int c = 0; c < 12; c++)
        #pragma unroll
        for (int j = 0; j < 4; j++)
            ur[c][j] = ub[c * 1024 + t + 256 * j];

    float blog[12];
    #pragma unroll
    for (int c = 0; c < 12; c++) blog[c] = 0.f;

    float s[4], v[4];
    for (int it = 0; it < 3; it++) {
        float mx = blog[0];
        #pragma unroll
        for (int c = 1; c < 12; c++) mx = fmaxf(mx, blog[c]);
        float cc[12], se = 0.f;
        #pragma unroll
        for (int c = 0; c < 12; c++) { cc[c] = expf(blog[c] - mx); se += cc[c]; }
        const float inv = 1.f / se;
        #pragma unroll
        for (int j = 0; j < 4; j++) s[j] = 0.f;
        #pragma unroll
        for (int c = 0; c < 12; c++) {
            float wgt = cc[c] * inv;
            #pragma unroll
            for (int j = 0; j < 4; j++) s[j] = fmaf(wgt, ur[c][j], s[j]);
        }
        float n2p = s[0]*s[0] + s[1]*s[1] + s[2]*s[2] + s[3]*s[3];
        float n2 = block_sum(n2p, sred);
        float nrm = sqrtf(n2);
        float scale = n2 / (1.f + n2) / (nrm + 1e-8f);
        #pragma unroll
        for (int j = 0; j < 4; j++) v[j] = scale * s[j];
        if (it < 2) {
            #pragma unroll
            for (int c = 0; c < 12; c++) {
                float p = ur[c][0]*v[0] + ur[c][1]*v[1] + ur[c][2]*v[2] + ur[c][3]*v[3];
                #pragma unroll
                for (int o = 16; o; o >>= 1) p += __shfl_xor_sync(0xffffffffu, p, o);
                if (lid == 0) s12[wid * 12 + c] = p;
            }
            __syncthreads();
            if (t < 12) {
                float a2 = 0.f;
                #pragma unroll
                for (int w2 = 0; w2 < 8; w2++) a2 += s12[w2 * 12 + t];
                sb12[t] = a2;
            }
            __syncthreads();
            #pragma unroll
            for (int c = 0; c < 12; c++) blog[c] += sb12[c];
            __syncthreads();
        }
    }

    size_t ob = (size_t)b * (A_ * DO);
    #pragma unroll
    for (int a = 0; a < A_; a++)
        #pragma unroll
        for (int j = 0; j < 4; j++)
            out[ob + (size_t)a * DO + t + 256 * j] = v[j];

    float mxp = fmaxf(fmaxf(s[0], s[1]), fmaxf(s[2], s[3]));
    float mxs = block_max(mxp, sred);
    float sep = expf(s[0]-mxs) + expf(s[1]-mxs) + expf(s[2]-mxs) + expf(s[3]-mxs);
    float sume = block_sum(sep, sred);
    float denom = sume + 1e-10f;
    float ep = 0.f;
    #pragma unroll
    for (int j = 0; j < 4; j++) {
        float pj = expf(s[j] - mxs) / denom;
        ep += pj * logf(pj + 1e-10f);
    }
    float H = -block_sum(ep, sred);
    H = fminf(fmaxf(H, 0.f), 10.f);
    if (t == 0) g_ent[b] = H;
}

// ===================== kernel 4: entropy loss scalar =====================
__global__ __launch_bounds__(256) void finalize_kernel(float* __restrict__ out, long idx) {
    __shared__ float sred[9];
    const int t = threadIdx.x;
    float sum = 0.f;
    for (int k = t; k < B_; k += 256) sum += g_ent[k];
    float total = block_sum(sum, sred);
    if (t == 0) {
        float mean = total / (float)B_;
        out[idx] = -0.4f / (1.f + expf(-mean));
    }
}

// ===================== launch =====================
extern "C" void kernel_launch(void* const* d_in, const int* in_sizes, int n_in,
                              void* d_out, int out_size) {
    const float* x    = (const float*)d_in[0];
    const float* W    = (const float*)d_in[1];
    const float* bias = (const float*)d_in[2];
    float* out = (float*)d_out;

    long total = NX + NW;
    split_kernel<<<(int)((total + 255) / 256), 256>>>(x, W);

    (void)cudaFuncSetAttribute(gemm_kernel, cudaFuncAttributeMaxDynamicSharedMemorySize, GEMM_SMEM);
    dim3 ggrid(NTOT / TN, B_ / TM);   // (48, 64)
    gemm_kernel<<<ggrid, 256, GEMM_SMEM>>>(bias);

    routing_kernel<<<B_, 256>>>(out);
    finalize_kernel<<<1, 256>>>(out, (long)out_size - 1);
}

// round 10
// speedup vs baseline: 2.2288x; 2.2288x over previous
#include <cuda_runtime.h>
#include <cuda_fp16.h>
#include <cstdint>

// ===================== problem sizes =====================
static constexpr int  B_   = 8192;
static constexpr int  C_   = 12;
static constexpr int  A_   = 8;
static constexpr int  DI   = 1024;
static constexpr int  DO   = 1024;
static constexpr int  NTOT = C_ * DO;        // 12288
static constexpr long NX   = (long)B_ * DI;      // 8388608
static constexpr long NW   = (long)NTOT * DI;    // 12582912
static constexpr float S_   = 64.f;              // mixing scale s
static constexpr float CMAIN = 1.f - 1.f / 64.f; // u = CMAIN*main + mix

// ===================== device scratch (no allocs allowed) ====================
// Row layout (2048 halves = 4096 bytes):
//   g_x[b] = [ xh | a2 ],  a2 = fp16(xh + s*xl)
//   g_w[n] = [ wh | b2 ],  b2 = fp16(wl + wh/s)
// phase 1 (iters 0..31):  main = xh . wh   (f32 acc)
// rescale: acc *= (1 - 1/s)
// phase 2 (iters 32..63): mix = a2 . b2    (adds cross terms, cancels main/s)
__device__ __half g_x[(size_t)B_ * 2 * DI];      // 33 MB
__device__ __half g_w[(size_t)NTOT * 2 * DI];    // 50 MB
__device__ float  g_u[(size_t)B_ * NTOT];        // 402 MB
__device__ float  g_ent[B_];

// ===================== helpers =====================
__device__ __forceinline__ uint32_t smem_u32(const void* p) {
    uint32_t a;
    asm("{ .reg .u64 t; cvta.to.shared.u64 t, %1; cvt.u32.u64 %0, t; }" : "=r"(a) : "l"(p));
    return a;
}
__device__ __forceinline__ void cp_async16(uint32_t smem_dst, const void* gsrc) {
    asm volatile("cp.async.cg.shared.global [%0], [%1], 16;" :: "r"(smem_dst), "l"(gsrc));
}
#define CP_COMMIT() asm volatile("cp.async.commit_group;" ::: "memory")
#define CP_WAIT(n)  asm volatile("cp.async.wait_group %0;" :: "n"(n) : "memory")

#define LDSM_X4(R0,R1,R2,R3,ADDR) \
    asm volatile("ldmatrix.sync.aligned.m8n8.x4.shared.b16 {%0,%1,%2,%3}, [%4];" \
                 : "=r"(R0),"=r"(R1),"=r"(R2),"=r"(R3) : "r"(ADDR))

#define MMA16816(C0,C1,C2,C3,A0,A1,A2,A3,B0,B1) \
    asm volatile("mma.sync.aligned.m16n8k16.row.col.f32.f16.f16.f32 " \
                 "{%0,%1,%2,%3}, {%4,%5,%6,%7}, {%8,%9}, {%0,%1,%2,%3};" \
                 : "+f"(C0),"+f"(C1),"+f"(C2),"+f"(C3) \
                 : "r"(A0),"r"(A1),"r"(A2),"r"(A3),"r"(B0),"r"(B1))

// ===================== kernel 1: split =====================
__global__ __launch_bounds__(256) void split_kernel(const float* __restrict__ x,
                                                    const float* __restrict__ W) {
    long i = (long)blockIdx.x * 256 + threadIdx.x;
    if (i < NX) {
        long b = i >> 10, k = i & 1023;
        float v = x[i];
        __half h = __float2half_rn(v);
        float hf = __half2float(h);
        float l = v - hf;                      // xl
        size_t base = (size_t)b * 2048;
        g_x[base + k]        = h;              // xh
        g_x[base + 1024 + k] = __float2half_rn(hf + S_ * l);   // a2
    } else {
        long j = i - NX;
        if (j < NW) {
            long n = j >> 10, k = j & 1023;
            float v = W[j];
            __half h = __float2half_rn(v);
            float hf = __half2float(h);
            float l = v - hf;                  // wl
            size_t base = (size_t)n * 2048;
            g_w[base + k]        = h;          // wh
            g_w[base + 1024 + k] = __float2half_rn(l + hf * (1.f / S_)); // b2
        }
    }
}

// ===================== kernel 2: HMMA GEMM  u = x @ W^T + bias =================
// CTA 128x256, 8 warps (2m x 4n) of 64x64, 64B data rows (+16B pad = 80B
// stride, conflict-free ldmatrix), 4-stage cp.async pipeline, 64 k-iters total.
static constexpr int TM = 128, TN = 256, STAGES = 4;
static constexpr int ROWB = 80;
static constexpr int ASTG = TM * ROWB;            // 10240
static constexpr int BSTG = TN * ROWB;            // 20480
static constexpr int STG  = ASTG + BSTG;          // 30720
static constexpr int GEMM_SMEM = STAGES * STG;    // 122880
static constexpr int KI = 32;                     // main iters (xh.wh)
static constexpr int KT = 64;                     // + 32 mix iters (a2.b2)

__global__ __launch_bounds__(256, 1) void gemm_kernel(const float* __restrict__ bias) {
    extern __shared__ char sm[];
    const uint32_t sb = smem_u32(sm);
    const int tid  = threadIdx.x;
    const int lane = tid & 31;
    const int w    = tid >> 5;
    const int wm   = w & 1;
    const int wn   = w >> 1;
    const long m0  = (long)blockIdx.y * TM;
    const long n0  = (long)blockIdx.x * TN;

    float acc[4][8][4];
    #pragma unroll
    for (int mt = 0; mt < 4; mt++)
        #pragma unroll
        for (int nt = 0; nt < 8; nt++)
            #pragma unroll
            for (int e = 0; e < 4; e++) acc[mt][nt][e] = 0.f;

    // ldmatrix per-lane bases
    const uint32_t rowA = (uint32_t)(wm * 64 + (lane & 7) + ((lane >> 3) & 1) * 8);
    const uint32_t colA = (uint32_t)(((lane >> 4) & 1) * 16);
    const uint32_t rowB = (uint32_t)(wn * 64 + (lane & 7) + ((lane >> 4) & 1) * 8);
    const uint32_t colB = (uint32_t)(((lane >> 3) & 1) * 16);

    const char* cx = (const char*)g_x;
    const char* cw = (const char*)g_w;

    // per-iter row = 64 data bytes = 4x16B granules; A 512 granules, B 1024.
    // kb = j*64 sweeps the whole 4096-byte row: [xh|a2] / [wh|b2].
    auto load_stage = [&](int j) {
        const uint32_t As = sb + (uint32_t)((j & 3) * STG);
        const uint32_t Bs = As + ASTG;
        const int kb = j * 64;
        #pragma unroll
        for (int it = 0; it < 2; it++) {
            int idx = tid + it * 256;             // < 512
            int r = idx >> 2, c = idx & 3;
            cp_async16(As + r * ROWB + c * 16, cx + (size_t)(m0 + r) * 4096 + kb + c * 16);
        }
        #pragma unroll
        for (int it = 0; it < 4; it++) {
            int idx = tid + it * 256;             // < 1024
            int r = idx >> 2, c = idx & 3;
            cp_async16(Bs + r * ROWB + c * 16, cw + (size_t)(n0 + r) * 4096 + kb + c * 16);
        }
    };

    #pragma unroll
    for (int j = 0; j < STAGES - 1; j++) { load_stage(j); CP_COMMIT(); }

    // -------- phase 1: main = xh . wh --------
    #pragma unroll 1
    for (int i = 0; i < KI; i++) {
        CP_WAIT(STAGES - 2);
        __syncthreads();
        load_stage(i + STAGES - 1);
        CP_COMMIT();
        const uint32_t As = sb + (uint32_t)((i & 3) * STG);
        const uint32_t Bs = As + ASTG;
        #pragma unroll
        for (int ks = 0; ks < 2; ks++) {
            uint32_t a[4][4], b[8][2];
            #pragma unroll
            for (int mt = 0; mt < 4; mt++) {
                uint32_t ad = As + (rowA + mt * 16) * ROWB + ks * 32 + colA;
                LDSM_X4(a[mt][0], a[mt][1], a[mt][2], a[mt][3], ad);
            }
            #pragma unroll
            for (int p = 0; p < 4; p++) {
                uint32_t bd = Bs + (rowB + p * 16) * ROWB + ks * 32 + colB;
                LDSM_X4(b[2*p][0], b[2*p][1], b[2*p+1][0], b[2*p+1][1], bd);
            }
            #pragma unroll
            for (int mt = 0; mt < 4; mt++)
                #pragma unroll
                for (int nt = 0; nt < 8; nt++)
                    MMA16816(acc[mt][nt][0], acc[mt][nt][1], acc[mt][nt][2], acc[mt][nt][3],
                             a[mt][0], a[mt][1], a[mt][2], a[mt][3],
                             b[nt][0], b[nt][1]);
        }
    }

    // u = (1 - 1/s)*main + mix  -> rescale main before phase 2
    #pragma unroll
    for (int mt = 0; mt < 4; mt++)
        #pragma unroll
        for (int nt = 0; nt < 8; nt++)
            #pragma unroll
            for (int e = 0; e < 4; e++)
                acc[mt][nt][e] *= CMAIN;

    // -------- phase 2: mix = a2 . b2 --------
    #pragma unroll 1
    for (int i = KI; i < KT; i++) {
        CP_WAIT(STAGES - 2);
        __syncthreads();
        if (i + STAGES - 1 < KT) load_stage(i + STAGES - 1);
        CP_COMMIT();
        const uint32_t As = sb + (uint32_t)((i & 3) * STG);
        const uint32_t Bs = As + ASTG;
        #pragma unroll
        for (int ks = 0; ks < 2; ks++) {
            uint32_t a[4][4], b[8][2];
            #pragma unroll
            for (int mt = 0; mt < 4; mt++) {
                uint32_t ad = As + (rowA + mt * 16) * ROWB + ks * 32 + colA;
                LDSM_X4(a[mt][0], a[mt][1], a[mt][2], a[mt][3], ad);
            }
            #pragma unroll
            for (int p = 0; p < 4; p++) {
                uint32_t bd = Bs + (rowB + p * 16) * ROWB + ks * 32 + colB;
                LDSM_X4(b[2*p][0], b[2*p][1], b[2*p+1][0], b[2*p+1][1], bd);
            }
            #pragma unroll
            for (int mt = 0; mt < 4; mt++)
                #pragma unroll
                for (int nt = 0; nt < 8; nt++)
                    MMA16816(acc[mt][nt][0], acc[mt][nt][1], acc[mt][nt][2], acc[mt][nt][3],
                             a[mt][0], a[mt][1], a[mt][2], a[mt][3],
                             b[nt][0], b[nt][1]);
        }
    }

    // epilogue: add bias, store fp32 to g_u
    #pragma unroll
    for (int nt = 0; nt < 8; nt++) {
        const long n = n0 + wn * 64 + nt * 8 + 2 * (lane & 3);
        const float2 bz = *(const float2*)&bias[n];
        #pragma unroll
        for (int mt = 0; mt < 4; mt++) {
            const long m = m0 + wm * 64 + mt * 16 + (lane >> 2);
            float2 lo = { acc[mt][nt][0] + bz.x, acc[mt][nt][1] + bz.y };
            float2 hi = { acc[mt][nt][2] + bz.x, acc[mt][nt][3] + bz.y };
            *(float2*)&g_u[(size_t)m * NTOT + n]       = lo;
            *(float2*)&g_u[(size_t)(m + 8) * NTOT + n] = hi;
        }
    }
}

// ===================== kernel 3: fused routing =====================
__device__ __forceinline__ float block_sum(float v, volatile float* smr) {
    int lane = threadIdx.x & 31, w = threadIdx.x >> 5;
    #pragma unroll
    for (int o = 16; o; o >>= 1) v += __shfl_xor_sync(0xffffffffu, v, o);
    if (lane == 0) smr[w] = v;
    __syncthreads();
    if (threadIdx.x == 0) {
        float s = smr[0];
        #pragma unroll
        for (int i = 1; i < 8; i++) s += smr[i];
        smr[8] = s;
    }
    __syncthreads();
    float r = smr[8];
    __syncthreads();
    return r;
}
__device__ __forceinline__ float block_max(float v, volatile float* smr) {
    int lane = threadIdx.x & 31, w = threadIdx.x >> 5;
    #pragma unroll
    for (int o = 16; o; o >>= 1) v = fmaxf(v, __shfl_xor_sync(0xffffffffu, v, o));
    if (lane == 0) smr[w] = v;
    __syncthreads();
    if (threadIdx.x == 0) {
        float s = smr[0];
        #pragma unroll
        for (int i = 1; i < 8; i++) s = fmaxf(s, smr[i]);
        smr[8] = s;
    }
    __syncthreads();
    float r = smr[8];
    __syncthreads();
    return r;
}

__global__ __launch_bounds__(256) void routing_kernel(float* __restrict__ out) {
    __shared__ float sred[9];
    __shared__ float s12[8 * 12];
    __shared__ float sb12[12];
    const int b = blockIdx.x;
    const int t = threadIdx.x;
    const int lid = t & 31, wid = t >> 5;

    float ur[12][4];
    const float* ub = g_u + (size_t)b * NTOT;
    #pragma unroll
    for (int c = 0; c < 12; c++)
        #pragma unroll
        for (int j = 0; j < 4; j++)
            ur[c][j] = ub[c * 1024 + t + 256 * j];

    float blog[12];
    #pragma unroll
    for (int c = 0; c < 12; c++) blog[c] = 0.f;

    float s[4], v[4];
    for (int it = 0; it < 3; it++) {
        float mx = blog[0];
        #pragma unroll
        for (int c = 1; c < 12; c++) mx = fmaxf(mx, blog[c]);
        float cc[12], se = 0.f;
        #pragma unroll
        for (int c = 0; c < 12; c++) { cc[c] = expf(blog[c] - mx); se += cc[c]; }
        const float inv = 1.f / se;
        #pragma unroll
        for (int j = 0; j < 4; j++) s[j] = 0.f;
        #pragma unroll
        for (int c = 0; c < 12; c++) {
            float wgt = cc[c] * inv;
            #pragma unroll
            for (int j = 0; j < 4; j++) s[j] = fmaf(wgt, ur[c][j], s[j]);
        }
        float n2p = s[0]*s[0] + s[1]*s[1] + s[2]*s[2] + s[3]*s[3];
        float n2 = block_sum(n2p, sred);
        float nrm = sqrtf(n2);
        float scale = n2 / (1.f + n2) / (nrm + 1e-8f);
        #pragma unroll
        for (int j = 0; j < 4; j++) v[j] = scale * s[j];
        if (it < 2) {
            #pragma unroll
            for (int c = 0; c < 12; c++) {
                float p = ur[c][0]*v[0] + ur[c][1]*v[1] + ur[c][2]*v[2] + ur[c][3]*v[3];
                #pragma unroll
                for (int o = 16; o; o >>= 1) p += __shfl_xor_sync(0xffffffffu, p, o);
                if (lid == 0) s12[wid * 12 + c] = p;
            }
            __syncthreads();
            if (t < 12) {
                float a2 = 0.f;
                #pragma unroll
                for (int w2 = 0; w2 < 8; w2++) a2 += s12[w2 * 12 + t];
                sb12[t] = a2;
            }
            __syncthreads();
            #pragma unroll
            for (int c = 0; c < 12; c++) blog[c] += sb12[c];
            __syncthreads();
        }
    }

    size_t ob = (size_t)b * (A_ * DO);
    #pragma unroll
    for (int a = 0; a < A_; a++)
        #pragma unroll
        for (int j = 0; j < 4; j++)
            out[ob + (size_t)a * DO + t + 256 * j] = v[j];

    float mxp = fmaxf(fmaxf(s[0], s[1]), fmaxf(s[2], s[3]));
    float mxs = block_max(mxp, sred);
    float sep = expf(s[0]-mxs) + expf(s[1]-mxs) + expf(s[2]-mxs) + expf(s[3]-mxs);
    float sume = block_sum(sep, sred);
    float denom = sume + 1e-10f;
    float ep = 0.f;
    #pragma unroll
    for (int j = 0; j < 4; j++) {
        float pj = expf(s[j] - mxs) / denom;
        ep += pj * logf(pj + 1e-10f);
    }
    float H = -block_sum(ep, sred);
    H = fminf(fmaxf(H, 0.f), 10.f);
    if (t == 0) g_ent[b] = H;
}

// ===================== kernel 4: entropy loss scalar =====================
__global__ __launch_bounds__(256) void finalize_kernel(float* __restrict__ out, long idx) {
    __shared__ float sred[9];
    const int t = threadIdx.x;
    float sum = 0.f;
    for (int k = t; k < B_; k += 256) sum += g_ent[k];
    float total = block_sum(sum, sred);
    if (t == 0) {
        float mean = total / (float)B_;
        out[idx] = -0.4f / (1.f + expf(-mean));
    }
}

// ===================== launch =====================
extern "C" void kernel_launch(void* const* d_in, const int* in_sizes, int n_in,
                              void* d_out, int out_size) {
    const float* x    = (const float*)d_in[0];
    const float* W    = (const float*)d_in[1];
    const float* bias = (const float*)d_in[2];
    float* out = (float*)d_out;

    long total = NX + NW;
    split_kernel<<<(int)((total + 255) / 256), 256>>>(x, W);

    (void)cudaFuncSetAttribute(gemm_kernel, cudaFuncAttributeMaxDynamicSharedMemorySize, GEMM_SMEM);
    dim3 ggrid(NTOT / TN, B_ / TM);   // (48, 64)
    gemm_kernel<<<ggrid, 256, GEMM_SMEM>>>(bias);

    routing_kernel<<<B_, 256>>>(out);
    finalize_kernel<<<1, 256>>>(out, (long)out_size - 1);
}